// round 13
// baseline (speedup 1.0000x reference)
#include <cuda_runtime.h>
#include <cuda_fp16.h>
#include <cstdint>
#include <cstddef>

#define NMAX 100000
#define EMAX 1600000
#define F    128
#define K2   256
#define MT   128            // nodes per GEMM tile
#define SCAN_CHUNK 1024
#define NBLK_SCAN  ((NMAX + SCAN_CHUNK - 1) / SCAN_CHUNK)

// x smem: [128 rows][264 fp16]  (528 B/row)
#define XSTR 264
// W smem: [128 cols][136 fp16]  (272 B/row)
#define WSTR 136

// smem byte offsets
#define S_BIAS 0
#define S_GAM  512
#define S_BET  1024
#define S_XH   2048
#define S_XL   (S_XH + 128 * XSTR * 2)          // 69632
#define S_WH   (S_XL + 128 * XSTR * 2)          // 137216
#define S_WL   (S_WH + 128 * WSTR * 2)          // 172032
#define S_END  (S_WL + 128 * WSTR * 2)          // 206848

// ---------------- scratch ------------------------------------------------------
__device__ int g_cnt[NMAX];
__device__ int g_off[NMAX];
__device__ int g_cur[NMAX];
__device__ int g_csr[EMAX];
__device__ uint4 g_wh[128 * 32];                 // W fp16 hi [col][256] = 512 B/col
__device__ uint4 g_wl[128 * 32];                 // W fp16 lo
__device__ uint4 g_hh[(size_t)(NMAX + MT) * 16]; // h fp16 hi [node][128]
__device__ uint4 g_hl[(size_t)(NMAX + MT) * 16]; // h fp16 lo
__device__ uint4 g_ahh[(size_t)(NMAX + MT) * 16];// ah fp16 hi
__device__ uint4 g_ahl[(size_t)(NMAX + MT) * 16];// ah fp16 lo
__device__ int g_bsum[NBLK_SCAN];
__device__ int g_bbase[NBLK_SCAN];

// ---------------- helpers ------------------------------------------------------
__device__ __forceinline__ uint32_t smem_u32(const void* p) {
    uint32_t a;
    asm("{ .reg .u64 t; cvta.to.shared.u64 t, %1; cvt.u32.u64 %0, t; }" : "=r"(a) : "l"(p));
    return a;
}
__device__ __forceinline__ uint32_t h2_as_u32(__half2 v) {
    return *reinterpret_cast<uint32_t*>(&v);
}
__device__ __forceinline__ uint4 pack8h(const float* f) {
    uint4 o;
    o.x = h2_as_u32(__floats2half2_rn(f[0], f[1]));
    o.y = h2_as_u32(__floats2half2_rn(f[2], f[3]));
    o.z = h2_as_u32(__floats2half2_rn(f[4], f[5]));
    o.w = h2_as_u32(__floats2half2_rn(f[6], f[7]));
    return o;
}
// fp16 split: f = hi + lo with hi = fp16(f), lo = fp16(f - hi)
__device__ __forceinline__ void split8h(const float* f, uint4& hi, uint4& lo) {
    float hf[8], lf[8];
    #pragma unroll
    for (int c = 0; c < 8; c++) {
        __half hv = __float2half_rn(f[c]);
        hf[c] = __half2float(hv);
        lf[c] = f[c] - hf[c];
    }
    hi = pack8h(hf);
    lo = pack8h(lf);
}
__device__ __forceinline__ void acc8(float* a, uint4 v) {
    float2 f0 = __half22float2(*reinterpret_cast<__half2*>(&v.x));
    float2 f1 = __half22float2(*reinterpret_cast<__half2*>(&v.y));
    float2 f2 = __half22float2(*reinterpret_cast<__half2*>(&v.z));
    float2 f3 = __half22float2(*reinterpret_cast<__half2*>(&v.w));
    a[0] += f0.x; a[1] += f0.y; a[2] += f1.x; a[3] += f1.y;
    a[4] += f2.x; a[5] += f2.y; a[6] += f3.x; a[7] += f3.y;
}
__device__ __forceinline__ void ldsm_x4(uint32_t* r, uint32_t addr) {
    asm volatile("ldmatrix.sync.aligned.m8n8.x4.shared.b16 {%0,%1,%2,%3}, [%4];"
                 : "=r"(r[0]), "=r"(r[1]), "=r"(r[2]), "=r"(r[3]) : "r"(addr));
}
__device__ __forceinline__ void ldsm_x2(uint32_t* r, uint32_t addr) {
    asm volatile("ldmatrix.sync.aligned.m8n8.x2.shared.b16 {%0,%1}, [%2];"
                 : "=r"(r[0]), "=r"(r[1]) : "r"(addr));
}
__device__ __forceinline__ void mma_f16(float* d, const uint32_t* a, const uint32_t* b) {
    asm volatile("mma.sync.aligned.m16n8k16.row.col.f32.f16.f16.f32 "
                 "{%0,%1,%2,%3}, {%4,%5,%6,%7}, {%8,%9}, {%0,%1,%2,%3};"
                 : "+f"(d[0]), "+f"(d[1]), "+f"(d[2]), "+f"(d[3])
                 : "r"(a[0]), "r"(a[1]), "r"(a[2]), "r"(a[3]), "r"(b[0]), "r"(b[1]));
}
__device__ __forceinline__ void cp16(uint32_t saddr, const void* gptr) {
    asm volatile("cp.async.cg.shared.global [%0], [%1], 16;"
                 :: "r"(saddr), "l"(gptr) : "memory");
}
__device__ __forceinline__ void cp_commit_wait_all() {
    asm volatile("cp.async.commit_group;\n cp.async.wait_group 0;" ::: "memory");
}

// ---------------- prep: split W into fp16 hi/lo [col][256] (512 B/col) -----------
__global__ void wsplit(const float* __restrict__ W) {
    int j = blockIdx.x;           // output col 0..127
    int q = threadIdx.x;          // 0..31 (8 k-values each)
    float f[8];
    *reinterpret_cast<float4*>(f)     = *reinterpret_cast<const float4*>(W + (size_t)j * K2 + q * 8);
    *reinterpret_cast<float4*>(f + 4) = *reinterpret_cast<const float4*>(W + (size_t)j * K2 + q * 8 + 4);
    uint4 hi, lo;
    split8h(f, hi, lo);
    g_wh[j * 32 + q] = hi;
    g_wl[j * 32 + q] = lo;
}

// ---------------- prep: h -> fp16 hi/lo -------------------------------------------
__global__ void hsplit(const float* __restrict__ h, int N) {
    int i = blockIdx.x * blockDim.x + threadIdx.x;   // one uint4 (8 halves) per thread
    if (i >= N * 16) return;
    float f[8];
    *reinterpret_cast<float4*>(f)     = *reinterpret_cast<const float4*>(h + (size_t)i * 8);
    *reinterpret_cast<float4*>(f + 4) = *reinterpret_cast<const float4*>(h + (size_t)i * 8 + 4);
    uint4 hi, lo;
    split8h(f, hi, lo);
    g_hh[i] = hi;
    g_hl[i] = lo;
}

// ---------------- prep: histogram / scan / fill ----------------------------------
__global__ void hist_dst(const int* __restrict__ dst, int E) {
    int i = blockIdx.x * blockDim.x + threadIdx.x;
    int e0 = i * 4;
    if (e0 + 4 <= E) {
        int4 d = *reinterpret_cast<const int4*>(dst + e0);
        atomicAdd(&g_cnt[d.x], 1);
        atomicAdd(&g_cnt[d.y], 1);
        atomicAdd(&g_cnt[d.z], 1);
        atomicAdd(&g_cnt[d.w], 1);
    } else {
        for (int e = e0; e < E; e++) atomicAdd(&g_cnt[dst[e]], 1);
    }
}
__global__ void scan_part1(int N) {
    const int b = blockIdx.x, tid = threadIdx.x;
    int i0 = b * SCAN_CHUNK + tid * 4;
    int s = 0;
    #pragma unroll
    for (int q = 0; q < 4; q++) { int i = i0 + q; if (i < N) s += g_cnt[i]; }
    #pragma unroll
    for (int o = 16; o > 0; o >>= 1) s += __shfl_xor_sync(0xffffffffu, s, o);
    __shared__ int ws[8];
    if ((tid & 31) == 0) ws[tid >> 5] = s;
    __syncthreads();
    if (tid == 0) {
        int t = 0;
        #pragma unroll
        for (int w = 0; w < 8; w++) t += ws[w];
        g_bsum[b] = t;
    }
}
__global__ void scan_part2(int nb) {
    const int tid = threadIdx.x, lane = tid & 31, wid = tid >> 5;
    int x = (tid < nb) ? g_bsum[tid] : 0;
    int inc = x;
    #pragma unroll
    for (int o = 1; o < 32; o <<= 1) {
        int t = __shfl_up_sync(0xffffffffu, inc, o);
        if (lane >= o) inc += t;
    }
    __shared__ int ws[4];
    if (lane == 31) ws[wid] = inc;
    __syncthreads();
    int wbase = 0;
    for (int w = 0; w < wid; w++) wbase += ws[w];
    if (tid < nb) g_bbase[tid] = wbase + inc - x;
}
__global__ void scan_part3(int N) {
    const int b = blockIdx.x, tid = threadIdx.x;
    const int lane = tid & 31, wid = tid >> 5;
    int i0 = b * SCAN_CHUNK + tid * 4;
    int v[4];
    #pragma unroll
    for (int q = 0; q < 4; q++) { int i = i0 + q; v[q] = (i < N) ? g_cnt[i] : 0; }
    int s = v[0] + v[1] + v[2] + v[3];
    int inc = s;
    #pragma unroll
    for (int o = 1; o < 32; o <<= 1) {
        int t = __shfl_up_sync(0xffffffffu, inc, o);
        if (lane >= o) inc += t;
    }
    __shared__ int ws[8], wse[8];
    if (lane == 31) ws[wid] = inc;
    __syncthreads();
    if (tid == 0) {
        int r = 0;
        #pragma unroll
        for (int w = 0; w < 8; w++) { wse[w] = r; r += ws[w]; }
    }
    __syncthreads();
    int run = g_bbase[b] + wse[wid] + (inc - s);
    #pragma unroll
    for (int q = 0; q < 4; q++) {
        int i = i0 + q;
        if (i < N) { g_off[i] = run; g_cur[i] = run; }
        run += v[q];
    }
}
__global__ void fill_csr(const int* __restrict__ src,
                         const int* __restrict__ dst, int E) {
    int i = blockIdx.x * blockDim.x + threadIdx.x;
    int e0 = i * 4;
    if (e0 + 4 <= E) {
        int4 s = *reinterpret_cast<const int4*>(src + e0);
        int4 d = *reinterpret_cast<const int4*>(dst + e0);
        g_csr[atomicAdd(&g_cur[d.x], 1)] = s.x;
        g_csr[atomicAdd(&g_cur[d.y], 1)] = s.y;
        g_csr[atomicAdd(&g_cur[d.z], 1)] = s.z;
        g_csr[atomicAdd(&g_cur[d.w], 1)] = s.w;
    } else {
        for (int e = e0; e < E; e++)
            g_csr[atomicAdd(&g_cur[dst[e]], 1)] = src[e];
    }
}

// ---------------- kernel A: convergent gather-mean over fp16 h -------------------
// Full warp per node; the two half-warps process edges t and t+1 of the SAME node
// (16 lanes x 16B cover one 256B fp16 row). Combine halves via shfl_xor(16).
__global__ __launch_bounds__(256)
void aggregate(int N) {
    const int n = blockIdx.x * 8 + (threadIdx.x >> 5);
    if (n >= N) return;
    const int lane = threadIdx.x & 31;
    const int half = lane >> 4;          // which edge of the pair
    const int c16  = lane & 15;          // 8 cols per lane
    const int beg = g_off[n];
    const int cnt = g_cnt[n];
    float a[8];
    #pragma unroll
    for (int c = 0; c < 8; c++) a[c] = 0.f;
    int t = 0;
    for (; t + 4 <= cnt; t += 4) {
        int e0 = __ldg(g_csr + beg + t + half);
        int e1 = __ldg(g_csr + beg + t + 2 + half);
        uint4 v0 = g_hh[(size_t)e0 * 16 + c16];
        uint4 v1 = g_hh[(size_t)e1 * 16 + c16];
        acc8(a, v0);
        acc8(a, v1);
    }
    for (; t < cnt; t += 2) {
        int e = t + half;
        if (e < cnt) {
            int s0 = __ldg(g_csr + beg + e);
            acc8(a, g_hh[(size_t)s0 * 16 + c16]);
        }
    }
    // combine the two halves (both end with the full sum)
    #pragma unroll
    for (int c = 0; c < 8; c++) a[c] += __shfl_xor_sync(0xffffffffu, a[c], 16);
    const float r = 1.0f / fmaxf((float)cnt, 1.0f);
    #pragma unroll
    for (int c = 0; c < 8; c++) a[c] *= r;
    uint4 hi, lo;
    split8h(a, hi, lo);
    if (half == 0) g_ahh[(size_t)n * 16 + c16] = hi;
    else           g_ahl[(size_t)n * 16 + c16] = lo;
}

// ---------------- kernel B: all-cp.async staged GEMM (mma.sync f16) + LN + ReLU --
__global__ __launch_bounds__(256, 1)
void fused_gemm(const float* __restrict__ bias,
                const float* __restrict__ gamma,
                const float* __restrict__ beta,
                float* __restrict__ out,
                int N) {
    extern __shared__ char smem[];
    const uint32_t sb  = smem_u32(smem);
    const int tid  = threadIdx.x;
    const int lane = tid & 31;
    const int warp = tid >> 5;            // 0..7; warp owns rows m0..m0+15
    const int m0   = warp * 16;
    const int tile0 = blockIdx.x * MT;
    const int nval  = min(MT, N - tile0);

    // ---- cp.async: W chunk0, x = [h | ah] both hi and lo ----
    {
        const char* whs = reinterpret_cast<const char*>(g_wh);
        const char* wls = reinterpret_cast<const char*>(g_wl);
        #pragma unroll
        for (int it = 0; it < 8; it++) {
            int i = it * 256 + tid;            // 2048 each
            int col = i >> 4, q = i & 15;
            cp16(sb + S_WH + col * (WSTR * 2) + q * 16, whs + col * 512 + q * 16);
            cp16(sb + S_WL + col * (WSTR * 2) + q * 16, wls + col * 512 + q * 16);
        }
        const char* hhs = reinterpret_cast<const char*>(g_hh + (size_t)tile0 * 16);
        const char* hls = reinterpret_cast<const char*>(g_hl + (size_t)tile0 * 16);
        const char* ahs = reinterpret_cast<const char*>(g_ahh + (size_t)tile0 * 16);
        const char* als = reinterpret_cast<const char*>(g_ahl + (size_t)tile0 * 16);
        #pragma unroll
        for (int it = 0; it < 8; it++) {
            int i = it * 256 + tid;            // 2048 each (128 rows x 16)
            int row = i >> 4, q = i & 15;
            uint32_t dx = sb + S_XH + row * (XSTR * 2) + q * 16;
            uint32_t dl = sb + S_XL + row * (XSTR * 2) + q * 16;
            size_t gb = (size_t)row * 256 + q * 16;
            cp16(dx,       hhs + gb);
            cp16(dl,       hls + gb);
            cp16(dx + 256, ahs + gb);
            cp16(dl + 256, als + gb);
        }
    }

    // params (regular loads, overlap with cp.async)
    if (tid < F) {
        *reinterpret_cast<float*>(smem + S_BIAS + tid * 4) = bias[tid];
        *reinterpret_cast<float*>(smem + S_GAM  + tid * 4) = gamma[tid];
        *reinterpret_cast<float*>(smem + S_BET  + tid * 4) = beta[tid];
    }

    cp_commit_wait_all();
    __syncthreads();

    // ---- GEMM via mma.sync f16, 3-term fp16 split, fp32 accum ----
    float acc[16][4];
    #pragma unroll
    for (int t = 0; t < 16; t++)
        #pragma unroll
        for (int c = 0; c < 4; c++) acc[t][c] = 0.f;

    const int agrp = lane >> 3, ar = lane & 7;
    const int arow = m0 + ar + ((agrp & 1) ? 8 : 0);
    const int akof = (agrp & 2) ? 8 : 0;
    const uint32_t a_off = (uint32_t)arow * (XSTR * 2) + akof * 2;
    const int l15 = lane & 15;
    const uint32_t b_off = (uint32_t)(l15 & 7) * (WSTR * 2) + ((l15 >> 3) ? 16 : 0);

    #pragma unroll
    for (int ch = 0; ch < 2; ch++) {
        if (ch == 1) {
            __syncthreads();   // all warps done reading W chunk 0
            const char* whs = reinterpret_cast<const char*>(g_wh);
            const char* wls = reinterpret_cast<const char*>(g_wl);
            #pragma unroll
            for (int it = 0; it < 8; it++) {
                int i = it * 256 + tid;
                int col = i >> 4, q = i & 15;
                cp16(sb + S_WH + col * (WSTR * 2) + q * 16, whs + col * 512 + 256 + q * 16);
                cp16(sb + S_WL + col * (WSTR * 2) + q * 16, wls + col * 512 + 256 + q * 16);
            }
            cp_commit_wait_all();
            __syncthreads();
        }
        #pragma unroll
        for (int s = 0; s < 8; s++) {
            const uint32_t kg = ch * 128 + s * 16;
            uint32_t ah4[4], al4[4];
            ldsm_x4(ah4, sb + S_XH + a_off + kg * 2);
            ldsm_x4(al4, sb + S_XL + a_off + kg * 2);
            #pragma unroll
            for (int t = 0; t < 16; t++) {
                const uint32_t bo = (uint32_t)t * 8 * (WSTR * 2) + b_off + s * 32;
                uint32_t bh[2], bl[2];
                ldsm_x2(bh, sb + S_WH + bo);
                mma_f16(acc[t], ah4, bh);
                mma_f16(acc[t], al4, bh);
                ldsm_x2(bl, sb + S_WL + bo);
                mma_f16(acc[t], ah4, bl);
            }
        }
    }

    // ---- epilogue: bias + LN (quad reduction) + affine + ReLU + store ----
    const int quad = lane >> 2;
    const int qid  = lane & 3;
    const int rl1  = m0 + quad;
    const int rl2  = rl1 + 8;

    #pragma unroll
    for (int t = 0; t < 16; t++) {
        const int c0 = t * 8 + qid * 2;
        float b0 = *reinterpret_cast<float*>(smem + S_BIAS + c0 * 4);
        float b1 = *reinterpret_cast<float*>(smem + S_BIAS + (c0 + 1) * 4);
        acc[t][0] += b0; acc[t][1] += b1;
        acc[t][2] += b0; acc[t][3] += b1;
    }
    float s1 = 0.f, s2 = 0.f;
    #pragma unroll
    for (int t = 0; t < 16; t++) { s1 += acc[t][0] + acc[t][1]; s2 += acc[t][2] + acc[t][3]; }
    s1 += __shfl_xor_sync(0xffffffffu, s1, 1);
    s1 += __shfl_xor_sync(0xffffffffu, s1, 2);
    s2 += __shfl_xor_sync(0xffffffffu, s2, 1);
    s2 += __shfl_xor_sync(0xffffffffu, s2, 2);
    const float mu1 = s1 * (1.0f / 128.0f), mu2 = s2 * (1.0f / 128.0f);
    float q1 = 0.f, q2 = 0.f;
    #pragma unroll
    for (int t = 0; t < 16; t++) {
        float d0 = acc[t][0] - mu1, d1 = acc[t][1] - mu1;
        float d2 = acc[t][2] - mu2, d3 = acc[t][3] - mu2;
        q1 += d0 * d0 + d1 * d1;
        q2 += d2 * d2 + d3 * d3;
    }
    q1 += __shfl_xor_sync(0xffffffffu, q1, 1);
    q1 += __shfl_xor_sync(0xffffffffu, q1, 2);
    q2 += __shfl_xor_sync(0xffffffffu, q2, 1);
    q2 += __shfl_xor_sync(0xffffffffu, q2, 2);
    const float inv1 = rsqrtf(q1 * (1.0f / 128.0f) + 1e-5f);
    const float inv2 = rsqrtf(q2 * (1.0f / 128.0f) + 1e-5f);

    const bool v1 = rl1 < nval, v2 = rl2 < nval;
    float* o1 = out + (size_t)(tile0 + rl1) * F;
    float* o2 = out + (size_t)(tile0 + rl2) * F;
    #pragma unroll
    for (int t = 0; t < 16; t++) {
        const int c0 = t * 8 + qid * 2;
        float g0 = *reinterpret_cast<float*>(smem + S_GAM + c0 * 4);
        float g1 = *reinterpret_cast<float*>(smem + S_GAM + (c0 + 1) * 4);
        float e0 = *reinterpret_cast<float*>(smem + S_BET + c0 * 4);
        float e1 = *reinterpret_cast<float*>(smem + S_BET + (c0 + 1) * 4);
        if (v1) {
            float2 r;
            r.x = fmaxf((acc[t][0] - mu1) * inv1 * g0 + e0, 0.0f);
            r.y = fmaxf((acc[t][1] - mu1) * inv1 * g1 + e1, 0.0f);
            *reinterpret_cast<float2*>(o1 + c0) = r;
        }
        if (v2) {
            float2 r;
            r.x = fmaxf((acc[t][2] - mu2) * inv2 * g0 + e0, 0.0f);
            r.y = fmaxf((acc[t][3] - mu2) * inv2 * g1 + e1, 0.0f);
            *reinterpret_cast<float2*>(o2 + c0) = r;
        }
    }
}

// ---------------- launch -----------------------------------------------------------
extern "C" void kernel_launch(void* const* d_in, const int* in_sizes, int n_in,
                              void* d_out, int out_size) {
    const float* h     = (const float*)d_in[0];
    const int*   src   = (const int*)  d_in[1];
    const int*   dst   = (const int*)  d_in[2];
    const float* W     = (const float*)d_in[3];
    const float* bias  = (const float*)d_in[4];
    const float* gamma = (const float*)d_in[5];
    const float* beta  = (const float*)d_in[6];
    float* out = (float*)d_out;

    const int N = in_sizes[0] / F;
    const int E = in_sizes[1];

    void* cnt_ptr = nullptr;
    cudaGetSymbolAddress(&cnt_ptr, g_cnt);
    cudaMemsetAsync(cnt_ptr, 0, (size_t)N * sizeof(int));

    wsplit<<<F, 32>>>(W);
    hsplit<<<(N * 16 + 255) / 256, 256>>>(h, N);
    hist_dst<<<(E / 4 + 255) / 256, 256>>>(dst, E);

    int nb = (N + SCAN_CHUNK - 1) / SCAN_CHUNK;
    scan_part1<<<nb, 256>>>(N);
    scan_part2<<<1, 128>>>(nb);
    scan_part3<<<nb, 256>>>(N);
    fill_csr<<<(E / 4 + 255) / 256, 256>>>(src, dst, E);

    aggregate<<<(N + 7) / 8, 256>>>(N);

    static int smem_set = 0;
    if (!smem_set) {
        cudaFuncSetAttribute(fused_gemm, cudaFuncAttributeMaxDynamicSharedMemorySize,
                             S_END);
        smem_set = 1;
    }
    int tiles = (N + MT - 1) / MT;
    fused_gemm<<<tiles, 256, S_END>>>(bias, gamma, beta, out, N);
}

// round 14
// speedup vs baseline: 1.0326x; 1.0326x over previous
#include <cuda_runtime.h>
#include <cuda_bf16.h>
#include <cstdint>
#include <cstddef>

#define NMAX 100000
#define EMAX 1600000
#define F    128
#define K2   256
#define MT   128            // nodes per GEMM tile
#define SCAN_CHUNK 1024
#define NBLK_SCAN  ((NMAX + SCAN_CHUNK - 1) / SCAN_CHUNK)   // 98
#define NB_PREP 296

// x smem: [128 rows][264 bf16]  (528 B/row)
#define XSTR 264
// W smem: [128 cols][136 bf16]  (272 B/row)
#define WSTR 136

// smem byte offsets
#define S_BIAS 0
#define S_GAM  512
#define S_BET  1024
#define S_XH   2048
#define S_XL   (S_XH + 128 * XSTR * 2)          // 69632
#define S_WH   (S_XL + 128 * XSTR * 2)          // 137216
#define S_WL   (S_WH + 128 * WSTR * 2)          // 172032
#define S_END  (S_WL + 128 * WSTR * 2)          // 206848

// ---------------- scratch ------------------------------------------------------
// g_cnt tail (indices NMAX..NMAX+15) holds grid-barrier counters; zeroed by the
// same cudaMemsetAsync that zeroes the counts, so barriers are per-launch fresh.
__device__ int g_cnt[NMAX + 16];
__device__ int g_off[NMAX];
__device__ int g_cur[NMAX];
__device__ int g_csr[EMAX];
__device__ unsigned long long g_wh[128 * 64];   // W bf16 hi [col][256] as u64x64
__device__ unsigned long long g_wl[128 * 64];   // W bf16 lo
// aggregated ah, bf16-split, row-major [node][128] (padded for tile overread)
__device__ unsigned long long g_ahh[(NMAX + MT) * 32];
__device__ unsigned long long g_ahl[(NMAX + MT) * 32];
__device__ int g_bsum[NBLK_SCAN];

// ---------------- helpers ------------------------------------------------------
__device__ __forceinline__ uint32_t smem_u32(const void* p) {
    uint32_t a;
    asm("{ .reg .u64 t; cvta.to.shared.u64 t, %1; cvt.u32.u64 %0, t; }" : "=r"(a) : "l"(p));
    return a;
}
__device__ __forceinline__ unsigned long long pk4(__nv_bfloat16 a, __nv_bfloat16 b,
                                                  __nv_bfloat16 c, __nv_bfloat16 d) {
    unsigned short u0 = __bfloat16_as_ushort(a), u1 = __bfloat16_as_ushort(b);
    unsigned short u2 = __bfloat16_as_ushort(c), u3 = __bfloat16_as_ushort(d);
    return (unsigned long long)u0 | ((unsigned long long)u1 << 16)
         | ((unsigned long long)u2 << 32) | ((unsigned long long)u3 << 48);
}
__device__ __forceinline__ void split4(float4 v, unsigned long long& hi,
                                       unsigned long long& lo) {
    __nv_bfloat16 hx = __float2bfloat16_rn(v.x), hy = __float2bfloat16_rn(v.y);
    __nv_bfloat16 hz = __float2bfloat16_rn(v.z), hw = __float2bfloat16_rn(v.w);
    __nv_bfloat16 lx = __float2bfloat16_rn(v.x - __bfloat162float(hx));
    __nv_bfloat16 ly = __float2bfloat16_rn(v.y - __bfloat162float(hy));
    __nv_bfloat16 lz = __float2bfloat16_rn(v.z - __bfloat162float(hz));
    __nv_bfloat16 lw = __float2bfloat16_rn(v.w - __bfloat162float(hw));
    hi = pk4(hx, hy, hz, hw);
    lo = pk4(lx, ly, lz, lw);
}
__device__ __forceinline__ void ldsm_x4(uint32_t* r, uint32_t addr) {
    asm volatile("ldmatrix.sync.aligned.m8n8.x4.shared.b16 {%0,%1,%2,%3}, [%4];"
                 : "=r"(r[0]), "=r"(r[1]), "=r"(r[2]), "=r"(r[3]) : "r"(addr));
}
__device__ __forceinline__ void ldsm_x2(uint32_t* r, uint32_t addr) {
    asm volatile("ldmatrix.sync.aligned.m8n8.x2.shared.b16 {%0,%1}, [%2];"
                 : "=r"(r[0]), "=r"(r[1]) : "r"(addr));
}
__device__ __forceinline__ void mma_bf16(float* d, const uint32_t* a, const uint32_t* b) {
    asm volatile("mma.sync.aligned.m16n8k16.row.col.f32.bf16.bf16.f32 "
                 "{%0,%1,%2,%3}, {%4,%5,%6,%7}, {%8,%9}, {%0,%1,%2,%3};"
                 : "+f"(d[0]), "+f"(d[1]), "+f"(d[2]), "+f"(d[3])
                 : "r"(a[0]), "r"(a[1]), "r"(a[2]), "r"(a[3]), "r"(b[0]), "r"(b[1]));
}
__device__ __forceinline__ void cp16(uint32_t saddr, const void* gptr) {
    asm volatile("cp.async.cg.shared.global [%0], [%1], 16;"
                 :: "r"(saddr), "l"(gptr) : "memory");
}
__device__ __forceinline__ void cp_commit_wait_all() {
    asm volatile("cp.async.commit_group;\n cp.async.wait_group 0;" ::: "memory");
}

// grid-wide barrier: monotonic counter in g_cnt tail (zeroed by host memset).
__device__ __forceinline__ void grid_bar(int idx) {
    __syncthreads();
    if (threadIdx.x == 0) {
        __threadfence();
        unsigned* c = reinterpret_cast<unsigned*>(&g_cnt[NMAX + idx]);
        atomicAdd(c, 1u);
        unsigned v;
        do {
            asm volatile("ld.acquire.gpu.u32 %0, [%1];" : "=r"(v) : "l"(c));
        } while (v < (unsigned)NB_PREP);
    }
    __syncthreads();
}

// ---------------- persistent prep: wsplit + hist + scan + fill (1 launch) --------
__global__ __launch_bounds__(256)
void prep(const float* __restrict__ W,
          const int* __restrict__ src,
          const int* __restrict__ dst,
          int N, int E) {
    const int tid = threadIdx.x;
    const int bid = blockIdx.x;
    const int gid = bid * 256 + tid;
    const int nth = NB_PREP * 256;

    // ---- phase A1: W transpose+split (8192 items) ----
    if (gid < 8192) {
        int j = gid >> 6;          // col 0..127
        int f4 = gid & 63;         // 4 k-values each
        float4 v = *reinterpret_cast<const float4*>(W + (size_t)j * K2 + f4 * 4);
        unsigned long long hi, lo;
        split4(v, hi, lo);
        g_wh[j * 64 + f4] = hi;
        g_wl[j * 64 + f4] = lo;
    }

    // ---- phase A2: degree histogram (int4) ----
    const int nq = E >> 2;
    for (int i = gid; i < nq; i += nth) {
        int4 d = reinterpret_cast<const int4*>(dst)[i];
        atomicAdd(&g_cnt[d.x], 1);
        atomicAdd(&g_cnt[d.y], 1);
        atomicAdd(&g_cnt[d.z], 1);
        atomicAdd(&g_cnt[d.w], 1);
    }
    for (int e = nq * 4 + gid; e < E; e += nth) atomicAdd(&g_cnt[dst[e]], 1);
    grid_bar(0);

    __shared__ int ws[8], wse[8];
    __shared__ int base_s;

    // ---- phase B: per-chunk sums (blocks 0..97) ----
    if (bid < NBLK_SCAN) {
        const int lane = tid & 31, wid = tid >> 5;
        int i0 = bid * SCAN_CHUNK + tid * 4;
        int s = 0;
        #pragma unroll
        for (int q = 0; q < 4; q++) { int i = i0 + q; if (i < N) s += g_cnt[i]; }
        int t = s;
        #pragma unroll
        for (int o = 16; o > 0; o >>= 1) t += __shfl_xor_sync(0xffffffffu, t, o);
        if (lane == 0) ws[wid] = t;
        __syncthreads();
        if (tid == 0) {
            int r = 0;
            #pragma unroll
            for (int w = 0; w < 8; w++) r += ws[w];
            g_bsum[bid] = r;
        }
    }
    grid_bar(1);

    // ---- phase C: offsets; each block locally prefixes the 98 chunk sums ----
    if (bid < NBLK_SCAN) {
        const int lane = tid & 31, wid = tid >> 5;
        if (tid == 0) {
            int b = 0;
            for (int i = 0; i < bid; i++) b += g_bsum[i];
            base_s = b;
        }
        int i0 = bid * SCAN_CHUNK + tid * 4;
        int v[4];
        #pragma unroll
        for (int q = 0; q < 4; q++) { int i = i0 + q; v[q] = (i < N) ? g_cnt[i] : 0; }
        int s = v[0] + v[1] + v[2] + v[3];
        int inc = s;
        #pragma unroll
        for (int o = 1; o < 32; o <<= 1) {
            int t = __shfl_up_sync(0xffffffffu, inc, o);
            if (lane >= o) inc += t;
        }
        if (lane == 31) ws[wid] = inc;
        __syncthreads();
        if (tid == 0) {
            int r = 0;
            #pragma unroll
            for (int w = 0; w < 8; w++) { wse[w] = r; r += ws[w]; }
        }
        __syncthreads();
        int run = base_s + wse[wid] + (inc - s);
        #pragma unroll
        for (int q = 0; q < 4; q++) {
            int i = i0 + q;
            if (i < N) { g_off[i] = run; g_cur[i] = run; }
            run += v[q];
        }
    }
    grid_bar(2);

    // ---- phase D: CSR fill (int4) ----
    for (int i = gid; i < nq; i += nth) {
        int4 s4 = reinterpret_cast<const int4*>(src)[i];
        int4 d4 = reinterpret_cast<const int4*>(dst)[i];
        g_csr[atomicAdd(&g_cur[d4.x], 1)] = s4.x;
        g_csr[atomicAdd(&g_cur[d4.y], 1)] = s4.y;
        g_csr[atomicAdd(&g_cur[d4.z], 1)] = s4.z;
        g_csr[atomicAdd(&g_cur[d4.w], 1)] = s4.w;
    }
    for (int e = nq * 4 + gid; e < E; e += nth)
        g_csr[atomicAdd(&g_cur[dst[e]], 1)] = src[e];
}

// ---------------- kernel A: high-occupancy fp32 gather-mean -> bf16-split ah -----
__global__ __launch_bounds__(256)
void aggregate(const float* __restrict__ h, int N) {
    const int n = blockIdx.x * 8 + (threadIdx.x >> 5);
    if (n >= N) return;
    const int lane = threadIdx.x & 31;
    const int j0 = lane * 4;
    const int beg = g_off[n];
    const int cnt = g_cnt[n];
    float4 a = make_float4(0.f, 0.f, 0.f, 0.f);
    int t = 0;
    for (; t + 4 <= cnt; t += 4) {
        int s0 = __ldg(g_csr + beg + t);
        int s1 = __ldg(g_csr + beg + t + 1);
        int s2 = __ldg(g_csr + beg + t + 2);
        int s3 = __ldg(g_csr + beg + t + 3);
        float4 v0 = *reinterpret_cast<const float4*>(h + (size_t)s0 * F + j0);
        float4 v1 = *reinterpret_cast<const float4*>(h + (size_t)s1 * F + j0);
        float4 v2 = *reinterpret_cast<const float4*>(h + (size_t)s2 * F + j0);
        float4 v3 = *reinterpret_cast<const float4*>(h + (size_t)s3 * F + j0);
        a.x += (v0.x + v1.x) + (v2.x + v3.x);
        a.y += (v0.y + v1.y) + (v2.y + v3.y);
        a.z += (v0.z + v1.z) + (v2.z + v3.z);
        a.w += (v0.w + v1.w) + (v2.w + v3.w);
    }
    for (; t < cnt; t++) {
        int s0 = __ldg(g_csr + beg + t);
        float4 v0 = *reinterpret_cast<const float4*>(h + (size_t)s0 * F + j0);
        a.x += v0.x; a.y += v0.y; a.z += v0.z; a.w += v0.w;
    }
    const float r = 1.0f / fmaxf((float)cnt, 1.0f);
    a.x *= r; a.y *= r; a.z *= r; a.w *= r;
    unsigned long long hi, lo;
    split4(a, hi, lo);
    g_ahh[(size_t)n * 32 + lane] = hi;
    g_ahl[(size_t)n * 32 + lane] = lo;
}

// ---------------- kernel B: staged GEMM (mma.sync) + LN + ReLU -------------------
__global__ __launch_bounds__(256, 1)
void fused_gemm(const float* __restrict__ h,
                const float* __restrict__ bias,
                const float* __restrict__ gamma,
                const float* __restrict__ beta,
                float* __restrict__ out,
                int N) {
    extern __shared__ char smem[];
    const uint32_t sb  = smem_u32(smem);
    const int tid  = threadIdx.x;
    const int lane = tid & 31;
    const int warp = tid >> 5;            // 0..7; warp owns rows m0..m0+15
    const int m0   = warp * 16;
    const int tile0 = blockIdx.x * MT;
    const int nval  = min(MT, N - tile0);

    // ---- cp.async: W chunk0 (hi+lo) and ah chunk (hi+lo) ----
    {
        const char* whs = reinterpret_cast<const char*>(g_wh);
        const char* wls = reinterpret_cast<const char*>(g_wl);
        #pragma unroll
        for (int it = 0; it < 8; it++) {
            int i = it * 256 + tid;            // 2048 each
            int col = i >> 4, q = i & 15;
            cp16(sb + S_WH + col * (WSTR * 2) + q * 16, whs + col * 512 + q * 16);
            cp16(sb + S_WL + col * (WSTR * 2) + q * 16, wls + col * 512 + q * 16);
        }
        const char* ahs = reinterpret_cast<const char*>(g_ahh + (size_t)tile0 * 32);
        const char* als = reinterpret_cast<const char*>(g_ahl + (size_t)tile0 * 32);
        #pragma unroll
        for (int it = 0; it < 8; it++) {
            int i = it * 256 + tid;            // 2048 each (128 rows x 16)
            int row = i >> 4, q = i & 15;
            cp16(sb + S_XH + row * (XSTR * 2) + F * 2 + q * 16, ahs + row * 256 + q * 16);
            cp16(sb + S_XL + row * (XSTR * 2) + F * 2 + q * 16, als + row * 256 + q * 16);
        }
    }

    // params (regular loads, overlap with cp.async)
    if (tid < F) {
        *reinterpret_cast<float*>(smem + S_BIAS + tid * 4) = bias[tid];
        *reinterpret_cast<float*>(smem + S_GAM  + tid * 4) = gamma[tid];
        *reinterpret_cast<float*>(smem + S_BET  + tid * 4) = beta[tid];
    }

    // ---- stage x (k 0..127) from fp32 h, bf16 split (exact; overlaps cp.async) ----
    #pragma unroll
    for (int it = 0; it < 16; it++) {
        int idx = it * 256 + tid;          // 4096 float4 slots
        int row = idx >> 5;
        int c   = idx & 31;                // float4 idx -> k0 = 4c
        float4 v = make_float4(0.f, 0.f, 0.f, 0.f);
        if (row < nval)
            v = *reinterpret_cast<const float4*>(h + (size_t)(tile0 + row) * F + c * 4);
        unsigned long long hi, lo;
        split4(v, hi, lo);
        *reinterpret_cast<unsigned long long*>(smem + S_XH + row * (XSTR * 2) + c * 8) = hi;
        *reinterpret_cast<unsigned long long*>(smem + S_XL + row * (XSTR * 2) + c * 8) = lo;
    }

    cp_commit_wait_all();
    __syncthreads();

    // ---- GEMM via mma.sync, 3-term bf16 split, fp32 accum ----
    float acc[16][4];
    #pragma unroll
    for (int t = 0; t < 16; t++)
        #pragma unroll
        for (int c = 0; c < 4; c++) acc[t][c] = 0.f;

    const int agrp = lane >> 3, ar = lane & 7;
    const int arow = m0 + ar + ((agrp & 1) ? 8 : 0);
    const int akof = (agrp & 2) ? 8 : 0;
    const uint32_t a_off = (uint32_t)arow * (XSTR * 2) + akof * 2;
    const int l15 = lane & 15;
    const uint32_t b_off = (uint32_t)(l15 & 7) * (WSTR * 2) + ((l15 >> 3) ? 16 : 0);

    #pragma unroll
    for (int ch = 0; ch < 2; ch++) {
        if (ch == 1) {
            __syncthreads();   // all warps done reading W chunk 0
            const char* whs = reinterpret_cast<const char*>(g_wh);
            const char* wls = reinterpret_cast<const char*>(g_wl);
            #pragma unroll
            for (int it = 0; it < 8; it++) {
                int i = it * 256 + tid;
                int col = i >> 4, q = i & 15;
                cp16(sb + S_WH + col * (WSTR * 2) + q * 16, whs + col * 512 + 256 + q * 16);
                cp16(sb + S_WL + col * (WSTR * 2) + q * 16, wls + col * 512 + 256 + q * 16);
            }
            cp_commit_wait_all();
            __syncthreads();
        }
        #pragma unroll
        for (int s = 0; s < 8; s++) {
            const uint32_t kg = ch * 128 + s * 16;
            uint32_t ah4[4], al4[4];
            ldsm_x4(ah4, sb + S_XH + a_off + kg * 2);
            ldsm_x4(al4, sb + S_XL + a_off + kg * 2);
            #pragma unroll
            for (int t = 0; t < 16; t++) {
                const uint32_t bo = (uint32_t)t * 8 * (WSTR * 2) + b_off + s * 32;
                uint32_t bh[2], bl[2];
                ldsm_x2(bh, sb + S_WH + bo);
                mma_bf16(acc[t], ah4, bh);
                mma_bf16(acc[t], al4, bh);
                ldsm_x2(bl, sb + S_WL + bo);
                mma_bf16(acc[t], ah4, bl);
            }
        }
    }

    // ---- epilogue: bias + LN (quad reduction) + affine + ReLU + store ----
    const int quad = lane >> 2;
    const int qid  = lane & 3;
    const int rl1  = m0 + quad;
    const int rl2  = rl1 + 8;

    #pragma unroll
    for (int t = 0; t < 16; t++) {
        const int c0 = t * 8 + qid * 2;
        float b0 = *reinterpret_cast<float*>(smem + S_BIAS + c0 * 4);
        float b1 = *reinterpret_cast<float*>(smem + S_BIAS + (c0 + 1) * 4);
        acc[t][0] += b0; acc[t][1] += b1;
        acc[t][2] += b0; acc[t][3] += b1;
    }
    float s1 = 0.f, s2 = 0.f;
    #pragma unroll
    for (int t = 0; t < 16; t++) { s1 += acc[t][0] + acc[t][1]; s2 += acc[t][2] + acc[t][3]; }
    s1 += __shfl_xor_sync(0xffffffffu, s1, 1);
    s1 += __shfl_xor_sync(0xffffffffu, s1, 2);
    s2 += __shfl_xor_sync(0xffffffffu, s2, 1);
    s2 += __shfl_xor_sync(0xffffffffu, s2, 2);
    const float mu1 = s1 * (1.0f / 128.0f), mu2 = s2 * (1.0f / 128.0f);
    float q1 = 0.f, q2 = 0.f;
    #pragma unroll
    for (int t = 0; t < 16; t++) {
        float d0 = acc[t][0] - mu1, d1 = acc[t][1] - mu1;
        float d2 = acc[t][2] - mu2, d3 = acc[t][3] - mu2;
        q1 += d0 * d0 + d1 * d1;
        q2 += d2 * d2 + d3 * d3;
    }
    q1 += __shfl_xor_sync(0xffffffffu, q1, 1);
    q1 += __shfl_xor_sync(0xffffffffu, q1, 2);
    q2 += __shfl_xor_sync(0xffffffffu, q2, 1);
    q2 += __shfl_xor_sync(0xffffffffu, q2, 2);
    const float inv1 = rsqrtf(q1 * (1.0f / 128.0f) + 1e-5f);
    const float inv2 = rsqrtf(q2 * (1.0f / 128.0f) + 1e-5f);

    const bool v1 = rl1 < nval, v2 = rl2 < nval;
    float* o1 = out + (size_t)(tile0 + rl1) * F;
    float* o2 = out + (size_t)(tile0 + rl2) * F;
    #pragma unroll
    for (int t = 0; t < 16; t++) {
        const int c0 = t * 8 + qid * 2;
        float g0 = *reinterpret_cast<float*>(smem + S_GAM + c0 * 4);
        float g1 = *reinterpret_cast<float*>(smem + S_GAM + (c0 + 1) * 4);
        float e0 = *reinterpret_cast<float*>(smem + S_BET + c0 * 4);
        float e1 = *reinterpret_cast<float*>(smem + S_BET + (c0 + 1) * 4);
        if (v1) {
            float2 r;
            r.x = fmaxf((acc[t][0] - mu1) * inv1 * g0 + e0, 0.0f);
            r.y = fmaxf((acc[t][1] - mu1) * inv1 * g1 + e1, 0.0f);
            *reinterpret_cast<float2*>(o1 + c0) = r;
        }
        if (v2) {
            float2 r;
            r.x = fmaxf((acc[t][2] - mu2) * inv2 * g0 + e0, 0.0f);
            r.y = fmaxf((acc[t][3] - mu2) * inv2 * g1 + e1, 0.0f);
            *reinterpret_cast<float2*>(o2 + c0) = r;
        }
    }
}

// ---------------- launch -----------------------------------------------------------
extern "C" void kernel_launch(void* const* d_in, const int* in_sizes, int n_in,
                              void* d_out, int out_size) {
    const float* h     = (const float*)d_in[0];
    const int*   src   = (const int*)  d_in[1];
    const int*   dst   = (const int*)  d_in[2];
    const float* W     = (const float*)d_in[3];
    const float* bias  = (const float*)d_in[4];
    const float* gamma = (const float*)d_in[5];
    const float* beta  = (const float*)d_in[6];
    float* out = (float*)d_out;

    const int N = in_sizes[0] / F;
    const int E = in_sizes[1];

    void* cnt_ptr = nullptr;
    cudaGetSymbolAddress(&cnt_ptr, g_cnt);
    // zero counts AND barrier counters (tail 16 ints)
    cudaMemsetAsync(cnt_ptr, 0, (size_t)(NMAX + 16) * sizeof(int));

    prep<<<NB_PREP, 256>>>(W, src, dst, N, E);
    aggregate<<<(N + 7) / 8, 256>>>(h, N);

    static int smem_set = 0;
    if (!smem_set) {
        cudaFuncSetAttribute(fused_gemm, cudaFuncAttributeMaxDynamicSharedMemorySize,
                             S_END);
        smem_set = 1;
    }
    int tiles = (N + MT - 1) / MT;
    fused_gemm<<<tiles, 256, S_END>>>(h, bias, gamma, beta, out, N);
}